// round 2
// baseline (speedup 1.0000x reference)
#include <cuda_runtime.h>
#include <cuda_bf16.h>

// Problem dims (fixed by the dataset)
#define HIDDEN 128
#define BATCH  4096
#define SESS   50
#define KDIM   4096

// Scratch (allocation-free rule: __device__ globals)
__device__ float g_R[BATCH * HIDDEN];  // gather-sum result
__device__ float g_T[BATCH * HIDDEN];  // A @ R

// ---------------------------------------------------------------------------
// Kernel 1: R[b, h] = sum_s item_embedding[items[b, s], h]
// One block per session row, 128 threads = one per hidden dim.
// items is int32 (JAX x64 disabled -> int64 request materializes as int32).
// ---------------------------------------------------------------------------
__global__ void gather_sum_kernel(const float* __restrict__ emb,
                                  const int* __restrict__ items,
                                  float* __restrict__ R) {
    const int row = blockIdx.x;
    const int h   = threadIdx.x;
    const int* it = items + row * SESS;
    float acc = 0.f;
#pragma unroll 5
    for (int s = 0; s < SESS; ++s) {
        const long long idx = (long long)it[s];
        acc += __ldg(&emb[idx * HIDDEN + h]);
    }
    R[row * HIDDEN + h] = acc;
}

// ---------------------------------------------------------------------------
// Kernel 2: C[M=4096, 128] = Amat[4096, 4096] @ Bmat[4096, 128]
// Specialized for N == 128 (full N per CTA). BM=32, BK=32, 256 threads.
// Thread (tx in [0,32), ty in [0,8)): cols tx*4..tx*4+3 (float4),
// rows ty + 8*r for r in 0..3  -> 4x4 accumulator tile.
// NORM: fused row-wise L2 normalization epilogue (each warp holds full rows).
// ---------------------------------------------------------------------------
template <bool NORM>
__global__ __launch_bounds__(256, 1)
void gemm_n128_kernel(const float* __restrict__ Amat,
                      const float* __restrict__ Bmat,
                      float* __restrict__ Cmat) {
    __shared__ float As[32][33];    // [k][m], padded (stride 33 avoids conflicts)
    __shared__ float Bs[32][HIDDEN];

    const int tid = threadIdx.x;
    const int tx  = tid & 31;       // 0..31 -> column group (4 cols each)
    const int ty  = tid >> 5;       // 0..7  -> base row
    const int m0  = blockIdx.x * 32;

    float acc[4][4] = {};

    for (int k0 = 0; k0 < KDIM; k0 += 32) {
        // --- Load A tile (32 rows x 32 k), store transposed As[k][m] ---
        {
            const int r  = tid >> 3;        // 0..31 (row within tile)
            const int kq = (tid & 7) * 4;   // k offset, float4
            float4 v = *(const float4*)&Amat[(long long)(m0 + r) * KDIM + k0 + kq];
            As[kq + 0][r] = v.x;
            As[kq + 1][r] = v.y;
            As[kq + 2][r] = v.z;
            As[kq + 3][r] = v.w;
        }
        // --- Load B tile (32 k x 128 n), float4 coalesced ---
        {
#pragma unroll
            for (int t = 0; t < 4; ++t) {
                const int slot = tid + t * 256;   // 0..1023 float4 slots
                const int br = slot >> 5;         // 0..31
                const int bc = (slot & 31) * 4;   // 0..124
                *(float4*)&Bs[br][bc] =
                    *(const float4*)&Bmat[(long long)(k0 + br) * HIDDEN + bc];
            }
        }
        __syncthreads();

#pragma unroll
        for (int k = 0; k < 32; ++k) {
            const float4 b = *(const float4*)&Bs[k][tx * 4];
            float a[4];
            a[0] = As[k][ty];
            a[1] = As[k][ty + 8];
            a[2] = As[k][ty + 16];
            a[3] = As[k][ty + 24];
#pragma unroll
            for (int r = 0; r < 4; ++r) {
                acc[r][0] += a[r] * b.x;
                acc[r][1] += a[r] * b.y;
                acc[r][2] += a[r] * b.z;
                acc[r][3] += a[r] * b.w;
            }
        }
        __syncthreads();
    }

    // --- Epilogue ---
#pragma unroll
    for (int r = 0; r < 4; ++r) {
        float scale = 1.0f;
        if (NORM) {
            // Row (m0 + ty + 8r) is fully held by the 32 lanes of this warp.
            float ss = acc[r][0] * acc[r][0] + acc[r][1] * acc[r][1]
                     + acc[r][2] * acc[r][2] + acc[r][3] * acc[r][3];
#pragma unroll
            for (int off = 16; off > 0; off >>= 1)
                ss += __shfl_xor_sync(0xFFFFFFFFu, ss, off);
            scale = 1.0f / sqrtf(ss);
        }
        const int row = m0 + ty + 8 * r;
        float4 o;
        o.x = acc[r][0] * scale;
        o.y = acc[r][1] * scale;
        o.z = acc[r][2] * scale;
        o.w = acc[r][3] * scale;
        *(float4*)&Cmat[(long long)row * HIDDEN + tx * 4] = o;
    }
}

// ---------------------------------------------------------------------------
// kernel_launch: inputs in metadata order:
//   d_in[0] item_embedding   f32 (100000, 128)
//   d_in[1] items            i32 (4096, 50)
//   d_in[2] A                f32 (4096, 4096)
//   d_in[3] D                f32 (4096, 4096)
//   d_in[4] target_embedding f32 (unused)
// Output: f32 (4096, 128)
// ---------------------------------------------------------------------------
extern "C" void kernel_launch(void* const* d_in, const int* in_sizes, int n_in,
                              void* d_out, int out_size) {
    const float* emb   = (const float*)d_in[0];
    const int*   items = (const int*)d_in[1];
    const float* A     = (const float*)d_in[2];
    const float* D     = (const float*)d_in[3];
    float*       out   = (float*)d_out;

    float* R;
    float* T;
    cudaGetSymbolAddress((void**)&R, g_R);
    cudaGetSymbolAddress((void**)&T, g_T);

    // R = gather-sum
    gather_sum_kernel<<<BATCH, HIDDEN>>>(emb, items, R);
    // T = A @ R
    gemm_n128_kernel<false><<<BATCH / 32, 256>>>(A, R, T);
    // out = normalize_rows(D @ T)   [ == normalize((D@A)@R) by associativity ]
    gemm_n128_kernel<true><<<BATCH / 32, 256>>>(D, T, out);
}

// round 4
// speedup vs baseline: 3.4591x; 3.4591x over previous
#include <cuda_runtime.h>
#include <cstdint>

// ---------------------------------------------------------------------------
// Problem dims (fixed by the dataset)
// ---------------------------------------------------------------------------
#define HIDDEN 128
#define BATCH  4096
#define SESS   50
#define KDIM   4096

// GEMM tiling
#define BM      32
#define BN      128
#define KC      32
#define NITER   (KDIM / KC)     // 128
#define STAGES  3
#define A_STRIDE 36             // words; stride%32==4 -> conflict-free A frags
#define B_STRIDE 136            // words; stride%32==8 -> conflict-free B frags
#define A_TILE_WORDS (BM * A_STRIDE)            // 1152
#define B_TILE_WORDS (KC * B_STRIDE)            // 4352
#define STAGE_WORDS  (A_TILE_WORDS + B_TILE_WORDS)
#define SMEM_BYTES   (STAGES * STAGE_WORDS * 4) // 66048
#define C_STRIDE 132            // words; stride%32==4 -> conflict-free readback

// Scratch (allocation-free rule: __device__ globals)
__device__ float g_R[BATCH * HIDDEN];  // gather-sum result  [b][h] == [k][n]
__device__ float g_T[BATCH * HIDDEN];  // A @ R              [b][h] == [k][n]

// ---------------------------------------------------------------------------
// PTX helpers (portable: sm_80+ instructions only, valid at compute_103)
// ---------------------------------------------------------------------------
__device__ __forceinline__ uint32_t smem_u32(const void* p) {
    uint32_t a;
    asm("{ .reg .u64 t; cvta.to.shared.u64 t, %1; cvt.u32.u64 %0, t; }" : "=r"(a) : "l"(p));
    return a;
}
__device__ __forceinline__ void cp_async16(uint32_t dst, const void* src) {
    asm volatile("cp.async.cg.shared.global [%0], [%1], 16;" :: "r"(dst), "l"(src));
}
__device__ __forceinline__ void cp_commit() {
    asm volatile("cp.async.commit_group;" ::: "memory");
}
template <int N>
__device__ __forceinline__ void cp_wait() {
    asm volatile("cp.async.wait_group %0;" :: "n"(N) : "memory");
}
__device__ __forceinline__ void mma_tf32(float* c,
                                         uint32_t a0, uint32_t a1, uint32_t a2, uint32_t a3,
                                         uint32_t b0, uint32_t b1) {
    asm volatile("mma.sync.aligned.m16n8k8.row.col.f32.tf32.tf32.f32 "
                 "{%0,%1,%2,%3}, {%4,%5,%6,%7}, {%8,%9}, {%0,%1,%2,%3};"
                 : "+f"(c[0]), "+f"(c[1]), "+f"(c[2]), "+f"(c[3])
                 : "r"(a0), "r"(a1), "r"(a2), "r"(a3), "r"(b0), "r"(b1));
}

// ---------------------------------------------------------------------------
// Kernel 1: R[b, h] = sum_s item_embedding[items[b, s], h]   (row-major [b][h])
// ---------------------------------------------------------------------------
__global__ void gather_sum_kernel(const float* __restrict__ emb,
                                  const int* __restrict__ items,
                                  float* __restrict__ R) {
    const int row = blockIdx.x;
    const int h   = threadIdx.x;
    const int* it = items + row * SESS;
    float acc = 0.f;
#pragma unroll 5
    for (int s = 0; s < SESS; ++s) {
        const long long idx = (long long)it[s];
        acc += __ldg(&emb[idx * HIDDEN + h]);
    }
    R[row * HIDDEN + h] = acc;
}

// ---------------------------------------------------------------------------
// tf32 mma.sync GEMM:  C[4096, 128] = Amat[4096, 4096] @ Bmat[4096, 128]
// Bmat row-major [K][N] feeds the col-major-in-k B fragment directly.
// 128 CTAs, 256 threads (8 warps, 2M x 4N), warp tile 16x32.
// NORM: fused row L2 normalization in the epilogue.
// ---------------------------------------------------------------------------
template <bool NORM>
__global__ __launch_bounds__(256, 1)
void gemm_mma_kernel(const float* __restrict__ Amat,
                     const float* __restrict__ Bmat,
                     float* __restrict__ Cmat) {
    extern __shared__ float sm[];
    const int tid  = threadIdx.x;
    const int wid  = tid >> 5;
    const int l    = tid & 31;
    const int quad = l >> 2;        // 0..7
    const int lq   = l & 3;         // 0..3
    const int wm   = wid & 1;       // M half (16 rows)
    const int wn   = wid >> 1;      // N quarter (32 cols)
    const int m0   = blockIdx.x * BM;
    const uint32_t smb = smem_u32(sm);

    // ---- stage loader (cp.async, one commit group per stage) ----
    auto load_stage = [&](int s, int chunk) {
        const int base = s * STAGE_WORDS;
        // A tile: 32 rows x 32 k -> 256 x 16B
        {
            const int row = tid >> 3;
            const int kq  = (tid & 7) * 4;
            cp_async16(smb + (uint32_t)((base + row * A_STRIDE + kq) * 4),
                       Amat + (size_t)(m0 + row) * KDIM + chunk * KC + kq);
        }
        // B tile: 32 k x 128 n -> 1024 x 16B
#pragma unroll
        for (int t = 0; t < 4; ++t) {
            const int slot = tid + t * 256;
            const int k    = slot >> 5;
            const int nq   = (slot & 31) * 4;
            cp_async16(smb + (uint32_t)((base + A_TILE_WORDS + k * B_STRIDE + nq) * 4),
                       Bmat + (size_t)(chunk * KC + k) * HIDDEN + nq);
        }
        cp_commit();
    };

    float acc[4][4] = {};

    load_stage(0, 0);
    load_stage(1, 1);

    for (int it = 0; it < NITER; ++it) {
        const int s = it % STAGES;
        cp_wait<STAGES - 2>();
        __syncthreads();
        // prefetch next-next chunk (overwrites the stage computed last iter;
        // the barrier above proves every warp is done with it)
        if (it + STAGES - 1 < NITER)
            load_stage((it + STAGES - 1) % STAGES, it + STAGES - 1);

        const float* As = sm + s * STAGE_WORDS;
        const float* Bs = As + A_TILE_WORDS;
#pragma unroll
        for (int ks = 0; ks < 4; ++ks) {
            const int k0 = ks * 8;
            const uint32_t a0 = __float_as_uint(As[(wm * 16 + quad) * A_STRIDE + k0 + lq]);
            const uint32_t a1 = __float_as_uint(As[(wm * 16 + quad + 8) * A_STRIDE + k0 + lq]);
            const uint32_t a2 = __float_as_uint(As[(wm * 16 + quad) * A_STRIDE + k0 + lq + 4]);
            const uint32_t a3 = __float_as_uint(As[(wm * 16 + quad + 8) * A_STRIDE + k0 + lq + 4]);
#pragma unroll
            for (int nt = 0; nt < 4; ++nt) {
                const int nb = wn * 32 + nt * 8 + quad;
                const uint32_t b0 = __float_as_uint(Bs[(k0 + lq) * B_STRIDE + nb]);
                const uint32_t b1 = __float_as_uint(Bs[(k0 + lq + 4) * B_STRIDE + nb]);
                mma_tf32(acc[nt], a0, a1, a2, a3, b0, b1);
            }
        }
    }

    // ---- Epilogue: stage buffers are dead; reuse smem as Cs[32][C_STRIDE] ----
    __syncthreads();
    float* Cs = sm;
#pragma unroll
    for (int nt = 0; nt < 4; ++nt) {
        const int col = wn * 32 + nt * 8 + 2 * lq;
        const int r0  = wm * 16 + quad;
        *(float2*)&Cs[r0 * C_STRIDE + col]       = make_float2(acc[nt][0], acc[nt][1]);
        *(float2*)&Cs[(r0 + 8) * C_STRIDE + col] = make_float2(acc[nt][2], acc[nt][3]);
    }
    __syncthreads();

#pragma unroll
    for (int i = 0; i < 4; ++i) {
        const int r = wid * 4 + i;
        float v0 = Cs[r * C_STRIDE + l];
        float v1 = Cs[r * C_STRIDE + l + 32];
        float v2 = Cs[r * C_STRIDE + l + 64];
        float v3 = Cs[r * C_STRIDE + l + 96];
        float scale = 1.0f;
        if (NORM) {
            float ss = v0 * v0 + v1 * v1 + v2 * v2 + v3 * v3;
#pragma unroll
            for (int off = 16; off > 0; off >>= 1)
                ss += __shfl_xor_sync(0xFFFFFFFFu, ss, off);
            scale = rsqrtf(ss);
        }
        float* dst = Cmat + (size_t)(m0 + r) * HIDDEN;
        dst[l]      = v0 * scale;
        dst[l + 32] = v1 * scale;
        dst[l + 64] = v2 * scale;
        dst[l + 96] = v3 * scale;
    }
}

// ---------------------------------------------------------------------------
// kernel_launch: inputs in metadata order:
//   d_in[0] item_embedding   f32 (100000, 128)
//   d_in[1] items            i32 (4096, 50)
//   d_in[2] A                f32 (4096, 4096)
//   d_in[3] D                f32 (4096, 4096)
//   d_in[4] target_embedding f32 (unused)
// Output: f32 (4096, 128)
// ---------------------------------------------------------------------------
extern "C" void kernel_launch(void* const* d_in, const int* in_sizes, int n_in,
                              void* d_out, int out_size) {
    const float* emb   = (const float*)d_in[0];
    const int*   items = (const int*)d_in[1];
    const float* A     = (const float*)d_in[2];
    const float* D     = (const float*)d_in[3];
    float*       out   = (float*)d_out;

    float *R, *T;
    cudaGetSymbolAddress((void**)&R, g_R);
    cudaGetSymbolAddress((void**)&T, g_T);

    cudaFuncSetAttribute(gemm_mma_kernel<false>,
                         cudaFuncAttributeMaxDynamicSharedMemorySize, SMEM_BYTES);
    cudaFuncSetAttribute(gemm_mma_kernel<true>,
                         cudaFuncAttributeMaxDynamicSharedMemorySize, SMEM_BYTES);

    // R = gather-sum
    gather_sum_kernel<<<BATCH, HIDDEN>>>(emb, items, R);
    // T = A @ R
    gemm_mma_kernel<false><<<BATCH / BM, 256, SMEM_BYTES>>>(A, R, T);
    // out = normalize_rows(D @ T)   [ == normalize((D@A)@R) by associativity ]
    gemm_mma_kernel<true><<<BATCH / BM, 256, SMEM_BYTES>>>(D, T, out);
}